// round 9
// baseline (speedup 1.0000x reference)
#include <cuda_runtime.h>
#include <cuda_bf16.h>

// Seq2Seq stacked GRU (L=64, H=64, D=128, B=128, T=256), wavefront-pipelined.
//  K1: precompute layer-0 input projections gi0 = x @ Wih0^T + bih0 (enc+dec)
//  K2: persistent wavefront kernel: 128 CTAs = 64 layers x 2 batch halves,
//      512 threads, gate-interleaved weights in SMEM, acquire/release flag
//      sync through L2, ring-buffered activations. Packed fma.rn.f32x2.
//  K3: output projection out = dec_top @ Wo^T + bo.

#define Hn    64
#define Ln    64
#define Dn    128
#define Bn    128
#define Tn    256
#define G3H   192
#define RINGN 4          // ring depth (power of two)
#define WSTR  194        // padded stride (gi0 kernel only)
#define HB    64         // batch rows per CTA (half of B)
#define WTH   512        // wave kernel threads

// Static device scratch (allocation-free rule: __device__ globals only)
__device__ float g_gi0[2][Tn][Bn][G3H];
__device__ float g_xbuf[Ln][2][RINGN][HB][Hn];
__device__ float g_dectop[Tn][Bn][Hn];
__device__ int   g_prog[Ln * 2];

__device__ __forceinline__ float sigf(float x) {
    return __fdividef(1.0f, 1.0f + __expf(-x));
}
__device__ __forceinline__ float tanhf_fast(float x) {
    return __fdividef(2.0f, 1.0f + __expf(-2.0f * x)) - 1.0f;
}

// ---- packed f32x2 helpers ------------------------------------------------
typedef unsigned long long u64;

__device__ __forceinline__ u64 pack2(float x) {
    u64 r;
    asm("mov.b64 %0, {%1, %1};" : "=l"(r) : "f"(x));
    return r;
}
__device__ __forceinline__ void fma2(u64& d, u64 a, u64 b) {
    asm("fma.rn.f32x2 %0, %1, %2, %0;" : "+l"(d) : "l"(a), "l"(b));
}
__device__ __forceinline__ float2 unpack2(u64 v) {
    float2 r;
    asm("mov.b64 {%0, %1}, %2;" : "=f"(r.x), "=f"(r.y) : "l"(v));
    return r;
}
__device__ __forceinline__ u64 ld2(const float* p) {
    return *(const u64*)p;
}

// ---- scoped acquire/release flag ops ------------------------------------
__device__ __forceinline__ int ld_acq(const int* p) {
    int v;
    asm volatile("ld.acquire.gpu.b32 %0, [%1];" : "=r"(v) : "l"(p) : "memory");
    return v;
}
__device__ __forceinline__ void st_rel(int* p, int v) {
    asm volatile("st.release.gpu.b32 [%0], %1;" :: "l"(p), "r"(v) : "memory");
}

// ---------------------------------------------------------------------------
// Kernel 1: gi0 for layer 0 of both GRUs. grid = (T, 2 halves, 2 models).
// ---------------------------------------------------------------------------
#define GI0_SMEM ((Dn * WSTR + HB * Dn) * 4)

__global__ void __launch_bounds__(256, 1) gi0_kernel(
    const float* __restrict__ ctx,
    const float* __restrict__ encW0, const float* __restrict__ decW0,
    const float* __restrict__ encB,  const float* __restrict__ decB)
{
    extern __shared__ float sm[];
    float* W_s = sm;                 // [Dn][WSTR] transposed
    float* x_s = W_s + Dn * WSTR;    // [HB][Dn]

    const int t = blockIdx.x, half = blockIdx.y, m = blockIdx.z;
    const float* W0 = m ? decW0 : encW0;
    const float* bi = m ? decB  : encB;
    const int tid = threadIdx.x;
    const int warp = tid >> 5, lane = tid & 31;
    const int bb = warp * 8, jj = lane * 2;

    for (int idx = tid; idx < G3H * Dn; idx += 256) {
        int j = idx >> 7, k = idx & 127;
        W_s[k * WSTR + j] = W0[idx];
    }
    const int tt = m ? (t - 1) : t;
    if (m && t == 0) {
        for (int idx = tid; idx < HB * Dn; idx += 256) x_s[idx] = 0.f;
    } else {
        for (int idx = tid; idx < HB * Dn; idx += 256) {
            int b = idx >> 7, k = idx & 127;
            x_s[idx] = ctx[((size_t)(half * HB + b) * Tn + tt) * Dn + k];
        }
    }
    __syncthreads();

    u64 ar[8], az[8], an[8];
#pragma unroll
    for (int i = 0; i < 8; i++) { ar[i] = 0ull; az[i] = 0ull; an[i] = 0ull; }

    for (int k0 = 0; k0 < Dn; k0 += 4) {
        u64 wr[4], wz[4], wn[4];
#pragma unroll
        for (int kk = 0; kk < 4; kk++) {
            const float* wrow = &W_s[(k0 + kk) * WSTR];
            wr[kk] = ld2(&wrow[jj]);
            wz[kk] = ld2(&wrow[64 + jj]);
            wn[kk] = ld2(&wrow[128 + jj]);
        }
#pragma unroll
        for (int i = 0; i < 8; i++) {
            float4 xv = *(const float4*)&x_s[(bb + i) * Dn + k0];
            u64 xp[4] = {pack2(xv.x), pack2(xv.y), pack2(xv.z), pack2(xv.w)};
#pragma unroll
            for (int kk = 0; kk < 4; kk++) {
                fma2(ar[i], xp[kk], wr[kk]);
                fma2(az[i], xp[kk], wz[kk]);
                fma2(an[i], xp[kk], wn[kk]);
            }
        }
    }
    float2 br = *(const float2*)&bi[jj];
    float2 bz = *(const float2*)&bi[64 + jj];
    float2 bn = *(const float2*)&bi[128 + jj];
#pragma unroll
    for (int i = 0; i < 8; i++) {
        int bg = half * HB + bb + i;
        float* dst = &g_gi0[m][t][bg][0];
        float2 vr = unpack2(ar[i]), vz = unpack2(az[i]), vn = unpack2(an[i]);
        *(float2*)&dst[jj]       = make_float2(vr.x + br.x, vr.y + br.y);
        *(float2*)&dst[64 + jj]  = make_float2(vz.x + bz.x, vz.y + bz.y);
        *(float2*)&dst[128 + jj] = make_float2(vn.x + bn.x, vn.y + bn.y);
    }
}

// ---------------------------------------------------------------------------
// Kernel 2: persistent wavefront GRU stack (encoder then decoder).
// Weight layout W6[k][j2][6]: 6 u64 per (k, j-pair):
//   s0..2 = Whh r,z,n (ur,uz,un); s3..5 = Wih r,z,n (wr,wz,wn).
// Group = 48 bytes, 16B-aligned; lane-strided LDS.128 is conflict-free.
// ---------------------------------------------------------------------------
#define W6F   (Hn * 32 * 6 * 2)                 // 24576 floats
#define WAVE_SMEM ((W6F + HB * Hn + HB * G3H + 4 * Hn) * 4)

__device__ __forceinline__ void stage_weights6(
    float* ws, float* cr_s, float* cz_s, float* bin_s, float* bhn_s,
    const float* __restrict__ Wih, const float* __restrict__ Whh,
    const float* __restrict__ bih, const float* __restrict__ bhh,
    int layer, bool isL0, int tid)
{
    const float* srch = Whh + (size_t)layer * G3H * Hn;
    for (int idx = tid; idx < G3H * Hn; idx += WTH) {
        int r = idx >> 6, c = idx & 63;        // Whh[r][c], r = g*64+j
        int g = r >> 6, j = r & 63;
        ws[((c * 32 + (j >> 1)) * 6 + g) * 2 + (j & 1)] = srch[idx];
    }
    if (!isL0) {
        const float* src = Wih + (size_t)(layer - 1) * G3H * Hn;
        for (int idx = tid; idx < G3H * Hn; idx += WTH) {
            int r = idx >> 6, c = idx & 63;
            int g = r >> 6, j = r & 63;
            ws[((c * 32 + (j >> 1)) * 6 + (g + 3)) * 2 + (j & 1)] = src[idx];
        }
    }
    if (tid < Hn) {
        int hj = tid;
        const float* bi = bih + layer * G3H;
        const float* bh = bhh + layer * G3H;
        cr_s[hj]  = (isL0 ? 0.f : bi[hj])      + bh[hj];
        cz_s[hj]  = (isL0 ? 0.f : bi[64 + hj]) + bh[64 + hj];
        bin_s[hj] = (isL0 ? 0.f : bi[128 + hj]);
        bhn_s[hj] = bh[128 + hj];
    }
}

__global__ void __launch_bounds__(WTH, 1) gru_wave(
    const float* __restrict__ encWih, const float* __restrict__ encWhh,
    const float* __restrict__ encBih, const float* __restrict__ encBhh,
    const float* __restrict__ decWih, const float* __restrict__ decWhh,
    const float* __restrict__ decBih, const float* __restrict__ decBhh)
{
    extern __shared__ float sm[];
    float* W6_s  = sm;                     // [64][32][6] u64-pairs (96 KB)
    float* h_s   = W6_s + W6F;             // [HB][Hn]
    float* x_s   = h_s + HB * Hn;          // [HB][Hn] or gi0 [HB][G3H] (l0)
    float* cr_s  = x_s + HB * G3H;
    float* cz_s  = cr_s + Hn;
    float* bin_s = cz_s + Hn;
    float* bhn_s = bin_s + Hn;

    const int tid   = threadIdx.x;
    const int cta   = blockIdx.x;
    const int layer = cta >> 1;
    const int half  = cta & 1;
    const bool isL0 = (layer == 0);
    const int warp = tid >> 5, lane = tid & 31;
    const int bb = warp * 4;          // 16 warps x 4 rows = 64
    const int jj = lane * 2;          // j-pair per lane

    const u64* W6u = (const u64*)W6_s;

    int base = 0;
    if (tid == 0) base = ld_acq(&g_prog[cta]);

    for (int i = tid; i < HB * Hn; i += WTH) h_s[i] = 0.f;   // h0 = 0
    stage_weights6(W6_s, cr_s, cz_s, bin_s, bhn_s,
                   encWih, encWhh, encBih, encBhh, layer, isL0, tid);
    __syncthreads();

    for (int t = 0; t < 2 * Tn; ++t) {
        if (t == Tn) {   // encoder -> decoder: swap weights, keep h (= h_n)
            stage_weights6(W6_s, cr_s, cz_s, bin_s, bhn_s,
                           decWih, decWhh, decBih, decBhh, layer, isL0, tid);
            __syncthreads();
        }
        // ---- sync: producer data ready / consumer slot free ----
        if (tid == 0) {
            if (layer > 0) {
                int tgt = base + t + 1;
                const int* p = &g_prog[cta - 2];
                while (ld_acq(p) < tgt) __nanosleep(64);
            }
            if (layer < Ln - 1 && t >= RINGN) {
                int tgt = base + t - RINGN + 1;
                const int* p = &g_prog[cta + 2];
                while (ld_acq(p) < tgt) __nanosleep(64);
            }
        }
        __syncthreads();

        // ---- stage input ----
        if (isL0) {
            int m  = (t < Tn) ? 0 : 1;
            int tt = (t < Tn) ? t : t - Tn;
            const float4* src = (const float4*)&g_gi0[m][tt][half * HB][0];
            float4* dst = (float4*)x_s;
            for (int i = tid; i < HB * G3H / 4; i += WTH) dst[i] = src[i];
        } else {
            const float4* src =
                (const float4*)&g_xbuf[layer - 1][half][t & (RINGN - 1)][0][0];
            float4* dst = (float4*)x_s;
            for (int i = tid; i < HB * Hn / 4; i += WTH) dst[i] = __ldcv(&src[i]);
        }
        __syncthreads();

        // ---- GEMMs (packed f32x2, interleaved weights) ----
        u64 ar[4], az[4], an[4], ahn[4];
#pragma unroll
        for (int i = 0; i < 4; i++) {
            ar[i] = 0ull; az[i] = 0ull; an[i] = 0ull; ahn[i] = 0ull;
        }

        if (!isL0) {
            for (int k0 = 0; k0 < Hn; k0 += 4) {
                float4 xv[4], hv[4];
#pragma unroll
                for (int i = 0; i < 4; i++) {
                    xv[i] = *(const float4*)&x_s[(bb + i) * Hn + k0];
                    hv[i] = *(const float4*)&h_s[(bb + i) * Hn + k0];
                }
#pragma unroll
                for (int kk = 0; kk < 4; kk++) {
                    const u64* wp = W6u + ((k0 + kk) * 32 + lane) * 6;
                    ulonglong2 w01 = *(const ulonglong2*)(wp);      // ur,uz
                    ulonglong2 w23 = *(const ulonglong2*)(wp + 2);  // un,wr
                    ulonglong2 w45 = *(const ulonglong2*)(wp + 4);  // wz,wn
                    float xk[4], hk[4];
#pragma unroll
                    for (int i = 0; i < 4; i++) {
                        xk[0] = xv[i].x; xk[1] = xv[i].y;
                        xk[2] = xv[i].z; xk[3] = xv[i].w;
                        hk[0] = hv[i].x; hk[1] = hv[i].y;
                        hk[2] = hv[i].z; hk[3] = hv[i].w;
                        u64 xp = pack2(xk[kk]);
                        u64 hp = pack2(hk[kk]);
                        fma2(ar[i],  hp, w01.x);
                        fma2(az[i],  hp, w01.y);
                        fma2(ahn[i], hp, w23.x);
                        fma2(ar[i],  xp, w23.y);
                        fma2(az[i],  xp, w45.x);
                        fma2(an[i],  xp, w45.y);
                    }
                }
            }
        } else {
            for (int k0 = 0; k0 < Hn; k0 += 4) {
                float4 hv[4];
#pragma unroll
                for (int i = 0; i < 4; i++)
                    hv[i] = *(const float4*)&h_s[(bb + i) * Hn + k0];
#pragma unroll
                for (int kk = 0; kk < 4; kk++) {
                    const u64* wp = W6u + ((k0 + kk) * 32 + lane) * 6;
                    ulonglong2 w01 = *(const ulonglong2*)(wp);      // ur,uz
                    u64 w2 = wp[2];                                 // un
                    float hk[4];
#pragma unroll
                    for (int i = 0; i < 4; i++) {
                        hk[0] = hv[i].x; hk[1] = hv[i].y;
                        hk[2] = hv[i].z; hk[3] = hv[i].w;
                        u64 hp = pack2(hk[kk]);
                        fma2(ar[i],  hp, w01.x);
                        fma2(az[i],  hp, w01.y);
                        fma2(ahn[i], hp, w2);
                    }
                }
            }
        }
        __syncthreads();   // all reads of h_s done before update

        // ---- epilogue: gates, h update, publish ----
        const bool wring = (layer < Ln - 1);
        const bool wtop  = (layer == Ln - 1) && (t >= Tn);
        float* rdst = &g_xbuf[layer][half][t & (RINGN - 1)][0][0];
        float* tdst = wtop ? &g_dectop[t - Tn][half * HB][0] : rdst;
        float2 crv = *(const float2*)&cr_s[jj];
        float2 czv = *(const float2*)&cz_s[jj];
        float2 biv = *(const float2*)&bin_s[jj];
        float2 bhv = *(const float2*)&bhn_s[jj];

#pragma unroll
        for (int i = 0; i < 4; i++) {
            int b = bb + i;
            float2 vr = unpack2(ar[i]);
            float2 vz = unpack2(az[i]);
            float2 vn = unpack2(an[i]);
            float2 vh = unpack2(ahn[i]);
            float arr[2] = {vr.x, vr.y}, azz[2] = {vz.x, vz.y};
            float ann[2] = {vn.x, vn.y}, ahh[2] = {vh.x, vh.y};
            float crr[2] = {crv.x, crv.y}, czz[2] = {czv.x, czv.y};
            float bii[2] = {biv.x, biv.y}, bhh2[2] = {bhv.x, bhv.y};
            float hnew2[2];
#pragma unroll
            for (int p = 0; p < 2; p++) {
                int hj = jj + p;
                float xr, xz, xn;
                if (isL0) {
                    xr = x_s[b * G3H + hj];
                    xz = x_s[b * G3H + 64 + hj];
                    xn = x_s[b * G3H + 128 + hj];
                } else {
                    xr = 0.f; xz = 0.f; xn = ann[p];
                }
                float r = sigf(arr[p] + xr + crr[p]);
                float z = sigf(azz[p] + xz + czz[p]);
                float n = tanhf_fast(xn + bii[p] + r * (ahh[p] + bhh2[p]));
                float hold = h_s[b * Hn + hj];
                hnew2[p] = (1.0f - z) * n + z * hold;
            }
            float2 hw = make_float2(hnew2[0], hnew2[1]);
            *(float2*)&h_s[b * Hn + jj] = hw;
            if (wring) *(float2*)&rdst[b * Hn + jj] = hw;
            if (wtop)  *(float2*)&tdst[b * Hn + jj] = hw;
        }
        __syncthreads();
        if (tid == 0) st_rel(&g_prog[cta], base + t + 1);
    }
}

// ---------------------------------------------------------------------------
// Kernel 3: output projection  out = dec_top @ Wo^T + bo. grid = (T, 2).
// ---------------------------------------------------------------------------
#define PSTR 130
#define PROJ_SMEM ((Hn * PSTR + HB * Hn) * 4)

__global__ void __launch_bounds__(256, 1) proj_kernel(
    const float* __restrict__ Wo, const float* __restrict__ bo,
    float* __restrict__ out)
{
    extern __shared__ float sm[];
    float* W_s = sm;                 // [64][PSTR] transposed
    float* x_s = W_s + Hn * PSTR;    // [HB][Hn]

    const int t = blockIdx.x, half = blockIdx.y;
    const int tid = threadIdx.x;
    const int warp = tid >> 5, lane = tid & 31;
    const int bb = warp * 8, jj = lane * 2;

    for (int idx = tid; idx < Dn * Hn; idx += 256) {
        int d = idx >> 6, k = idx & 63;
        W_s[k * PSTR + d] = Wo[idx];
    }
    for (int idx = tid; idx < HB * Hn; idx += 256) {
        x_s[idx] = g_dectop[t][half * HB + (idx >> 6)][idx & 63];
    }
    __syncthreads();

    u64 a0[8], a1[8];
#pragma unroll
    for (int i = 0; i < 8; i++) { a0[i] = 0ull; a1[i] = 0ull; }

    for (int k0 = 0; k0 < Hn; k0 += 4) {
        u64 w0[4], w1[4];
#pragma unroll
        for (int kk = 0; kk < 4; kk++) {
            const float* wrow = &W_s[(k0 + kk) * PSTR];
            w0[kk] = ld2(&wrow[jj]);
            w1[kk] = ld2(&wrow[64 + jj]);
        }
#pragma unroll
        for (int i = 0; i < 8; i++) {
            float4 xv = *(const float4*)&x_s[(bb + i) * Hn + k0];
            u64 xp[4] = {pack2(xv.x), pack2(xv.y), pack2(xv.z), pack2(xv.w)};
#pragma unroll
            for (int kk = 0; kk < 4; kk++) {
                fma2(a0[i], xp[kk], w0[kk]);
                fma2(a1[i], xp[kk], w1[kk]);
            }
        }
    }
    float2 b0 = *(const float2*)&bo[jj];
    float2 b1 = *(const float2*)&bo[64 + jj];
#pragma unroll
    for (int i = 0; i < 8; i++) {
        int bg = half * HB + bb + i;
        float* o = &out[((size_t)bg * Tn + t) * Dn];
        float2 v0 = unpack2(a0[i]), v1 = unpack2(a1[i]);
        *(float2*)&o[jj]      = make_float2(v0.x + b0.x, v0.y + b0.y);
        *(float2*)&o[64 + jj] = make_float2(v1.x + b1.x, v1.y + b1.y);
    }
}

// ---------------------------------------------------------------------------
extern "C" void kernel_launch(void* const* d_in, const int* in_sizes, int n_in,
                              void* d_out, int out_size) {
    const float* ctx     = (const float*)d_in[0];
    const float* encW0   = (const float*)d_in[1];
    const float* encWih  = (const float*)d_in[2];
    const float* encWhh  = (const float*)d_in[3];
    const float* encBih  = (const float*)d_in[4];
    const float* encBhh  = (const float*)d_in[5];
    const float* decW0   = (const float*)d_in[6];
    const float* decWih  = (const float*)d_in[7];
    const float* decWhh  = (const float*)d_in[8];
    const float* decBih  = (const float*)d_in[9];
    const float* decBhh  = (const float*)d_in[10];
    const float* Wo      = (const float*)d_in[11];
    const float* bo      = (const float*)d_in[12];
    float* out = (float*)d_out;

    cudaFuncSetAttribute(gi0_kernel,
        cudaFuncAttributeMaxDynamicSharedMemorySize, GI0_SMEM);
    cudaFuncSetAttribute(gru_wave,
        cudaFuncAttributeMaxDynamicSharedMemorySize, WAVE_SMEM);
    cudaFuncSetAttribute(proj_kernel,
        cudaFuncAttributeMaxDynamicSharedMemorySize, PROJ_SMEM);

    gi0_kernel<<<dim3(Tn, 2, 2), 256, GI0_SMEM>>>(ctx, encW0, decW0,
                                                  encBih, decBih);
    gru_wave<<<Ln * 2, WTH, WAVE_SMEM>>>(encWih, encWhh, encBih, encBhh,
                                         decWih, decWhh, decBih, decBhh);
    proj_kernel<<<dim3(Tn, 2), 256, PROJ_SMEM>>>(Wo, bo, out);
}

// round 11
// speedup vs baseline: 1.5289x; 1.5289x over previous
#include <cuda_runtime.h>
#include <cuda_bf16.h>

// Seq2Seq stacked GRU (L=64, H=64, D=128, B=128, T=256), wavefront-pipelined.
//  K1: precompute layer-0 input projections gi0 = x @ Wih0^T + bih0 (enc+dec)
//  K2: persistent wavefront kernel: 128 CTAs = 64 layers x 2 batch halves,
//      512 threads with j-split warp tiling (warp = row-group x j-half),
//      weights in SMEM (WSTR stride, conflict-free), acquire/release flag
//      sync through L2, ring-buffered activations. Packed fma.rn.f32x2.
//  K3: output projection out = dec_top @ Wo^T + bo.

#define Hn    64
#define Ln    64
#define Dn    128
#define Bn    128
#define Tn    256
#define G3H   192
#define RINGN 4          // ring depth (power of two)
#define WSTR  194        // padded SMEM stride for transposed weights (even)
#define HB    64         // batch rows per CTA (half of B)
#define WTH   512        // wave kernel threads

// Static device scratch (allocation-free rule: __device__ globals only)
__device__ float g_gi0[2][Tn][Bn][G3H];
__device__ float g_xbuf[Ln][2][RINGN][HB][Hn];
__device__ float g_dectop[Tn][Bn][Hn];
__device__ int   g_prog[Ln * 2];

__device__ __forceinline__ float sigf(float x) {
    return __fdividef(1.0f, 1.0f + __expf(-x));
}
__device__ __forceinline__ float tanhf_fast(float x) {
    return __fdividef(2.0f, 1.0f + __expf(-2.0f * x)) - 1.0f;
}

// ---- packed f32x2 helpers ------------------------------------------------
typedef unsigned long long u64;

__device__ __forceinline__ u64 pack2(float x) {
    u64 r;
    asm("mov.b64 %0, {%1, %1};" : "=l"(r) : "f"(x));
    return r;
}
__device__ __forceinline__ void fma2(u64& d, u64 a, u64 b) {
    asm("fma.rn.f32x2 %0, %1, %2, %0;" : "+l"(d) : "l"(a), "l"(b));
}
__device__ __forceinline__ float2 unpack2(u64 v) {
    float2 r;
    asm("mov.b64 {%0, %1}, %2;" : "=f"(r.x), "=f"(r.y) : "l"(v));
    return r;
}
__device__ __forceinline__ u64 ld2(const float* p) {
    return *(const u64*)p;
}

// ---- scoped acquire/release flag ops ------------------------------------
__device__ __forceinline__ int ld_acq(const int* p) {
    int v;
    asm volatile("ld.acquire.gpu.b32 %0, [%1];" : "=r"(v) : "l"(p) : "memory");
    return v;
}
__device__ __forceinline__ void st_rel(int* p, int v) {
    asm volatile("st.release.gpu.b32 [%0], %1;" :: "l"(p), "r"(v) : "memory");
}

// ---------------------------------------------------------------------------
// Kernel 1: gi0 for layer 0 of both GRUs. grid = (T, 2 halves, 2 models).
// ---------------------------------------------------------------------------
#define GI0_SMEM ((Dn * WSTR + HB * Dn) * 4)

__global__ void __launch_bounds__(256, 1) gi0_kernel(
    const float* __restrict__ ctx,
    const float* __restrict__ encW0, const float* __restrict__ decW0,
    const float* __restrict__ encB,  const float* __restrict__ decB)
{
    extern __shared__ float sm[];
    float* W_s = sm;                 // [Dn][WSTR] transposed
    float* x_s = W_s + Dn * WSTR;    // [HB][Dn]

    const int t = blockIdx.x, half = blockIdx.y, m = blockIdx.z;
    const float* W0 = m ? decW0 : encW0;
    const float* bi = m ? decB  : encB;
    const int tid = threadIdx.x;
    const int warp = tid >> 5, lane = tid & 31;
    const int bb = warp * 8, jj = lane * 2;

    for (int idx = tid; idx < G3H * Dn; idx += 256) {
        int j = idx >> 7, k = idx & 127;
        W_s[k * WSTR + j] = W0[idx];
    }
    const int tt = m ? (t - 1) : t;
    if (m && t == 0) {
        for (int idx = tid; idx < HB * Dn; idx += 256) x_s[idx] = 0.f;
    } else {
        for (int idx = tid; idx < HB * Dn; idx += 256) {
            int b = idx >> 7, k = idx & 127;
            x_s[idx] = ctx[((size_t)(half * HB + b) * Tn + tt) * Dn + k];
        }
    }
    __syncthreads();

    u64 ar[8], az[8], an[8];
#pragma unroll
    for (int i = 0; i < 8; i++) { ar[i] = 0ull; az[i] = 0ull; an[i] = 0ull; }

    for (int k0 = 0; k0 < Dn; k0 += 4) {
        u64 wr[4], wz[4], wn[4];
#pragma unroll
        for (int kk = 0; kk < 4; kk++) {
            const float* wrow = &W_s[(k0 + kk) * WSTR];
            wr[kk] = ld2(&wrow[jj]);
            wz[kk] = ld2(&wrow[64 + jj]);
            wn[kk] = ld2(&wrow[128 + jj]);
        }
#pragma unroll
        for (int i = 0; i < 8; i++) {
            float4 xv = *(const float4*)&x_s[(bb + i) * Dn + k0];
            u64 xp[4] = {pack2(xv.x), pack2(xv.y), pack2(xv.z), pack2(xv.w)};
#pragma unroll
            for (int kk = 0; kk < 4; kk++) {
                fma2(ar[i], xp[kk], wr[kk]);
                fma2(az[i], xp[kk], wz[kk]);
                fma2(an[i], xp[kk], wn[kk]);
            }
        }
    }
    float2 br = *(const float2*)&bi[jj];
    float2 bz = *(const float2*)&bi[64 + jj];
    float2 bn = *(const float2*)&bi[128 + jj];
#pragma unroll
    for (int i = 0; i < 8; i++) {
        int bg = half * HB + bb + i;
        float* dst = &g_gi0[m][t][bg][0];
        float2 vr = unpack2(ar[i]), vz = unpack2(az[i]), vn = unpack2(an[i]);
        *(float2*)&dst[jj]       = make_float2(vr.x + br.x, vr.y + br.y);
        *(float2*)&dst[64 + jj]  = make_float2(vz.x + bz.x, vz.y + bz.y);
        *(float2*)&dst[128 + jj] = make_float2(vn.x + bn.x, vn.y + bn.y);
    }
}

// ---------------------------------------------------------------------------
// Kernel 2: persistent wavefront GRU stack (encoder then decoder).
// 512 threads. Warp w: row-group rg = w >> 1 (8 rows), j-half jh = w & 1.
// Lane: r2 = lane >> 4 picks 4-row subset; jj = jh*32 + (lane & 15)*2.
// Weight LDS per warp-instr touches one 128B segment (half-warp broadcast);
// each warp reads only its j-half of the weights.
// ---------------------------------------------------------------------------
#define WAVE_SMEM ((Hn * WSTR * 2 + HB * Hn + HB * G3H + 4 * Hn) * 4)

__device__ __forceinline__ void stage_weights(
    float* Wih_s, float* Whh_s, float* cr_s, float* cz_s,
    float* bin_s, float* bhn_s,
    const float* __restrict__ Wih, const float* __restrict__ Whh,
    const float* __restrict__ bih, const float* __restrict__ bhh,
    int layer, bool isL0, int tid)
{
    if (!isL0) {
        const float* src = Wih + (size_t)(layer - 1) * G3H * Hn;
        for (int idx = tid; idx < G3H * Hn; idx += WTH) {
            int j = idx >> 6, k = idx & 63;
            Wih_s[k * WSTR + j] = src[idx];
        }
    }
    const float* srch = Whh + (size_t)layer * G3H * Hn;
    for (int idx = tid; idx < G3H * Hn; idx += WTH) {
        int j = idx >> 6, k = idx & 63;
        Whh_s[k * WSTR + j] = srch[idx];
    }
    if (tid < Hn) {
        int hj = tid;
        const float* bi = bih + layer * G3H;
        const float* bh = bhh + layer * G3H;
        cr_s[hj]  = (isL0 ? 0.f : bi[hj])      + bh[hj];
        cz_s[hj]  = (isL0 ? 0.f : bi[64 + hj]) + bh[64 + hj];
        bin_s[hj] = (isL0 ? 0.f : bi[128 + hj]);
        bhn_s[hj] = bh[128 + hj];
    }
}

__global__ void __launch_bounds__(WTH, 1) gru_wave(
    const float* __restrict__ encWih, const float* __restrict__ encWhh,
    const float* __restrict__ encBih, const float* __restrict__ encBhh,
    const float* __restrict__ decWih, const float* __restrict__ decWhh,
    const float* __restrict__ decBih, const float* __restrict__ decBhh)
{
    extern __shared__ float sm[];
    float* Wih_s = sm;                       // [64][WSTR]
    float* Whh_s = Wih_s + Hn * WSTR;        // [64][WSTR]
    float* h_s   = Whh_s + Hn * WSTR;        // [HB][Hn]
    float* x_s   = h_s + HB * Hn;            // [HB][Hn] or gi0 [HB][G3H] (l0)
    float* cr_s  = x_s + HB * G3H;
    float* cz_s  = cr_s + Hn;
    float* bin_s = cz_s + Hn;
    float* bhn_s = bin_s + Hn;

    const int tid   = threadIdx.x;
    const int cta   = blockIdx.x;
    const int layer = cta >> 1;
    const int half  = cta & 1;
    const bool isL0 = (layer == 0);
    const int warp = tid >> 5, lane = tid & 31;
    const int rg = warp >> 1;                 // row-group 0..7 (8 rows each)
    const int jh = warp & 1;                  // j-half 0..1
    const int bb = rg * 8 + (lane >> 4) * 4;  // 4 rows: bb..bb+3
    const int jj = jh * 32 + (lane & 15) * 2; // j-pair index in [0,64)

    int base = 0;
    if (tid == 0) base = ld_acq(&g_prog[cta]);

    for (int i = tid; i < HB * Hn; i += WTH) h_s[i] = 0.f;   // h0 = 0
    stage_weights(Wih_s, Whh_s, cr_s, cz_s, bin_s, bhn_s,
                  encWih, encWhh, encBih, encBhh, layer, isL0, tid);
    __syncthreads();

    for (int t = 0; t < 2 * Tn; ++t) {
        if (t == Tn) {   // encoder -> decoder: swap weights, keep h (= h_n)
            stage_weights(Wih_s, Whh_s, cr_s, cz_s, bin_s, bhn_s,
                          decWih, decWhh, decBih, decBhh, layer, isL0, tid);
            __syncthreads();
        }
        // ---- sync: producer data ready / consumer slot free ----
        if (tid == 0) {
            if (layer > 0) {
                int tgt = base + t + 1;
                const int* p = &g_prog[cta - 2];
                while (ld_acq(p) < tgt) __nanosleep(64);
            }
            if (layer < Ln - 1 && t >= RINGN) {
                int tgt = base + t - RINGN + 1;
                const int* p = &g_prog[cta + 2];
                while (ld_acq(p) < tgt) __nanosleep(64);
            }
        }
        __syncthreads();

        // ---- stage input ----
        if (isL0) {
            int m  = (t < Tn) ? 0 : 1;
            int tt = (t < Tn) ? t : t - Tn;
            const float4* src = (const float4*)&g_gi0[m][tt][half * HB][0];
            float4* dst = (float4*)x_s;
            for (int i = tid; i < HB * G3H / 4; i += WTH) dst[i] = src[i];
        } else {
            const float4* src =
                (const float4*)&g_xbuf[layer - 1][half][t & (RINGN - 1)][0][0];
            float4* dst = (float4*)x_s;
            for (int i = tid; i < HB * Hn / 4; i += WTH) dst[i] = __ldcv(&src[i]);
        }
        __syncthreads();

        // ---- GEMMs (packed f32x2) ----
        u64 ar[4], az[4], an[4], ahn[4];
#pragma unroll
        for (int i = 0; i < 4; i++) {
            ar[i] = 0ull; az[i] = 0ull; an[i] = 0ull; ahn[i] = 0ull;
        }

        if (!isL0) {
            for (int k0 = 0; k0 < Hn; k0 += 4) {
                u64 wr[4], wz[4], wn[4], ur[4], uz[4], un[4];
#pragma unroll
                for (int kk = 0; kk < 4; kk++) {
                    const float* a = &Wih_s[(k0 + kk) * WSTR];
                    const float* b = &Whh_s[(k0 + kk) * WSTR];
                    wr[kk] = ld2(&a[jj]);
                    wz[kk] = ld2(&a[64 + jj]);
                    wn[kk] = ld2(&a[128 + jj]);
                    ur[kk] = ld2(&b[jj]);
                    uz[kk] = ld2(&b[64 + jj]);
                    un[kk] = ld2(&b[128 + jj]);
                }
#pragma unroll
                for (int i = 0; i < 4; i++) {
                    float4 xv = *(const float4*)&x_s[(bb + i) * Hn + k0];
                    float4 hv = *(const float4*)&h_s[(bb + i) * Hn + k0];
                    float xk[4] = {xv.x, xv.y, xv.z, xv.w};
                    float hk[4] = {hv.x, hv.y, hv.z, hv.w};
#pragma unroll
                    for (int kk = 0; kk < 4; kk++) {
                        u64 xp = pack2(xk[kk]);
                        u64 hp = pack2(hk[kk]);
                        fma2(ar[i], xp, wr[kk]);
                        fma2(ar[i], hp, ur[kk]);
                        fma2(az[i], xp, wz[kk]);
                        fma2(az[i], hp, uz[kk]);
                        fma2(an[i], xp, wn[kk]);
                        fma2(ahn[i], hp, un[kk]);
                    }
                }
            }
        } else {
            for (int k0 = 0; k0 < Hn; k0 += 4) {
                u64 ur[4], uz[4], un[4];
#pragma unroll
                for (int kk = 0; kk < 4; kk++) {
                    const float* b = &Whh_s[(k0 + kk) * WSTR];
                    ur[kk] = ld2(&b[jj]);
                    uz[kk] = ld2(&b[64 + jj]);
                    un[kk] = ld2(&b[128 + jj]);
                }
#pragma unroll
                for (int i = 0; i < 4; i++) {
                    float4 hv = *(const float4*)&h_s[(bb + i) * Hn + k0];
                    float hk[4] = {hv.x, hv.y, hv.z, hv.w};
#pragma unroll
                    for (int kk = 0; kk < 4; kk++) {
                        u64 hp = pack2(hk[kk]);
                        fma2(ar[i], hp, ur[kk]);
                        fma2(az[i], hp, uz[kk]);
                        fma2(ahn[i], hp, un[kk]);
                    }
                }
            }
        }
        __syncthreads();   // all reads of h_s done before update

        // ---- epilogue: gates, h update, publish ----
        const bool wring = (layer < Ln - 1);
        const bool wtop  = (layer == Ln - 1) && (t >= Tn);
        float* rdst = &g_xbuf[layer][half][t & (RINGN - 1)][0][0];
        float* tdst = wtop ? &g_dectop[t - Tn][half * HB][0] : rdst;
        float2 crv = *(const float2*)&cr_s[jj];
        float2 czv = *(const float2*)&cz_s[jj];
        float2 biv = *(const float2*)&bin_s[jj];
        float2 bhv = *(const float2*)&bhn_s[jj];

#pragma unroll
        for (int i = 0; i < 4; i++) {
            int b = bb + i;
            float2 vr = unpack2(ar[i]);
            float2 vz = unpack2(az[i]);
            float2 vn = unpack2(an[i]);
            float2 vh = unpack2(ahn[i]);
            float arr[2] = {vr.x, vr.y}, azz[2] = {vz.x, vz.y};
            float ann[2] = {vn.x, vn.y}, ahh[2] = {vh.x, vh.y};
            float crr[2] = {crv.x, crv.y}, czz[2] = {czv.x, czv.y};
            float bii[2] = {biv.x, biv.y}, bhh2[2] = {bhv.x, bhv.y};
            float hnew2[2];
#pragma unroll
            for (int p = 0; p < 2; p++) {
                int hj = jj + p;
                float xr, xz, xn;
                if (isL0) {
                    xr = x_s[b * G3H + hj];
                    xz = x_s[b * G3H + 64 + hj];
                    xn = x_s[b * G3H + 128 + hj];
                } else {
                    xr = 0.f; xz = 0.f; xn = ann[p];
                }
                float r = sigf(arr[p] + xr + crr[p]);
                float z = sigf(azz[p] + xz + czz[p]);
                float n = tanhf_fast(xn + bii[p] + r * (ahh[p] + bhh2[p]));
                float hold = h_s[b * Hn + hj];
                hnew2[p] = (1.0f - z) * n + z * hold;
            }
            float2 hw = make_float2(hnew2[0], hnew2[1]);
            *(float2*)&h_s[b * Hn + jj] = hw;
            if (wring) *(float2*)&rdst[b * Hn + jj] = hw;
            if (wtop)  *(float2*)&tdst[b * Hn + jj] = hw;
        }
        __syncthreads();
        if (tid == 0) st_rel(&g_prog[cta], base + t + 1);
    }
}

// ---------------------------------------------------------------------------
// Kernel 3: output projection  out = dec_top @ Wo^T + bo. grid = (T, 2).
// ---------------------------------------------------------------------------
#define PSTR 130
#define PROJ_SMEM ((Hn * PSTR + HB * Hn) * 4)

__global__ void __launch_bounds__(256, 1) proj_kernel(
    const float* __restrict__ Wo, const float* __restrict__ bo,
    float* __restrict__ out)
{
    extern __shared__ float sm[];
    float* W_s = sm;                 // [64][PSTR] transposed
    float* x_s = W_s + Hn * PSTR;    // [HB][Hn]

    const int t = blockIdx.x, half = blockIdx.y;
    const int tid = threadIdx.x;
    const int warp = tid >> 5, lane = tid & 31;
    const int bb = warp * 8, jj = lane * 2;

    for (int idx = tid; idx < Dn * Hn; idx += 256) {
        int d = idx >> 6, k = idx & 63;
        W_s[k * PSTR + d] = Wo[idx];
    }
    for (int idx = tid; idx < HB * Hn; idx += 256) {
        x_s[idx] = g_dectop[t][half * HB + (idx >> 6)][idx & 63];
    }
    __syncthreads();

    u64 a0[8], a1[8];
#pragma unroll
    for (int i = 0; i < 8; i++) { a0[i] = 0ull; a1[i] = 0ull; }

    for (int k0 = 0; k0 < Hn; k0 += 4) {
        u64 w0[4], w1[4];
#pragma unroll
        for (int kk = 0; kk < 4; kk++) {
            const float* wrow = &W_s[(k0 + kk) * PSTR];
            w0[kk] = ld2(&wrow[jj]);
            w1[kk] = ld2(&wrow[64 + jj]);
        }
#pragma unroll
        for (int i = 0; i < 8; i++) {
            float4 xv = *(const float4*)&x_s[(bb + i) * Hn + k0];
            u64 xp[4] = {pack2(xv.x), pack2(xv.y), pack2(xv.z), pack2(xv.w)};
#pragma unroll
            for (int kk = 0; kk < 4; kk++) {
                fma2(a0[i], xp[kk], w0[kk]);
                fma2(a1[i], xp[kk], w1[kk]);
            }
        }
    }
    float2 b0 = *(const float2*)&bo[jj];
    float2 b1 = *(const float2*)&bo[64 + jj];
#pragma unroll
    for (int i = 0; i < 8; i++) {
        int bg = half * HB + bb + i;
        float* o = &out[((size_t)bg * Tn + t) * Dn];
        float2 v0 = unpack2(a0[i]), v1 = unpack2(a1[i]);
        *(float2*)&o[jj]      = make_float2(v0.x + b0.x, v0.y + b0.y);
        *(float2*)&o[64 + jj] = make_float2(v1.x + b1.x, v1.y + b1.y);
    }
}

// ---------------------------------------------------------------------------
extern "C" void kernel_launch(void* const* d_in, const int* in_sizes, int n_in,
                              void* d_out, int out_size) {
    const float* ctx     = (const float*)d_in[0];
    const float* encW0   = (const float*)d_in[1];
    const float* encWih  = (const float*)d_in[2];
    const float* encWhh  = (const float*)d_in[3];
    const float* encBih  = (const float*)d_in[4];
    const float* encBhh  = (const float*)d_in[5];
    const float* decW0   = (const float*)d_in[6];
    const float* decWih  = (const float*)d_in[7];
    const float* decWhh  = (const float*)d_in[8];
    const float* decBih  = (const float*)d_in[9];
    const float* decBhh  = (const float*)d_in[10];
    const float* Wo      = (const float*)d_in[11];
    const float* bo      = (const float*)d_in[12];
    float* out = (float*)d_out;

    cudaFuncSetAttribute(gi0_kernel,
        cudaFuncAttributeMaxDynamicSharedMemorySize, GI0_SMEM);
    cudaFuncSetAttribute(gru_wave,
        cudaFuncAttributeMaxDynamicSharedMemorySize, WAVE_SMEM);
    cudaFuncSetAttribute(proj_kernel,
        cudaFuncAttributeMaxDynamicSharedMemorySize, PROJ_SMEM);

    gi0_kernel<<<dim3(Tn, 2, 2), 256, GI0_SMEM>>>(ctx, encW0, decW0,
                                                  encBih, decBih);
    gru_wave<<<Ln * 2, WTH, WAVE_SMEM>>>(encWih, encWhh, encBih, encBhh,
                                         decWih, decWhh, decBih, decBhh);
    proj_kernel<<<dim3(Tn, 2), 256, PROJ_SMEM>>>(Wo, bo, out);
}

// round 12
// speedup vs baseline: 1.5472x; 1.0120x over previous
#include <cuda_runtime.h>
#include <cuda_bf16.h>

// Seq2Seq stacked GRU (L=64, H=64, D=128, B=128, T=256), wavefront-pipelined.
//  K1: precompute layer-0 input projections gi0 = x @ Wih0^T + bih0 (enc+dec)
//  K2: persistent wavefront kernel: 128 CTAs = 64 layers x 2 batch halves,
//      512 threads, j-split warp tiling, double-buffered h/x (2 barriers per
//      step), early flag release, overlap staging with flag machinery.
//  K3: output projection out = dec_top @ Wo^T + bo.

#define Hn    64
#define Ln    64
#define Dn    128
#define Bn    128
#define Tn    256
#define G3H   192
#define RINGN 4          // ring depth (power of two)
#define WSTR  194        // padded SMEM stride for transposed weights (even)
#define HB    64         // batch rows per CTA (half of B)
#define WTH   512        // wave kernel threads

// Static device scratch (allocation-free rule: __device__ globals only)
__device__ float g_gi0[2][Tn][Bn][G3H];
__device__ float g_xbuf[Ln][2][RINGN][HB][Hn];
__device__ float g_dectop[Tn][Bn][Hn];
__device__ int   g_prog[Ln * 2];

__device__ __forceinline__ float sigf(float x) {
    return __fdividef(1.0f, 1.0f + __expf(-x));
}
__device__ __forceinline__ float tanhf_fast(float x) {
    return __fdividef(2.0f, 1.0f + __expf(-2.0f * x)) - 1.0f;
}

// ---- packed f32x2 helpers ------------------------------------------------
typedef unsigned long long u64;

__device__ __forceinline__ u64 pack2(float x) {
    u64 r;
    asm("mov.b64 %0, {%1, %1};" : "=l"(r) : "f"(x));
    return r;
}
__device__ __forceinline__ void fma2(u64& d, u64 a, u64 b) {
    asm("fma.rn.f32x2 %0, %1, %2, %0;" : "+l"(d) : "l"(a), "l"(b));
}
__device__ __forceinline__ float2 unpack2(u64 v) {
    float2 r;
    asm("mov.b64 {%0, %1}, %2;" : "=f"(r.x), "=f"(r.y) : "l"(v));
    return r;
}
__device__ __forceinline__ u64 ld2(const float* p) {
    return *(const u64*)p;
}

// ---- scoped acquire/release flag ops ------------------------------------
__device__ __forceinline__ int ld_acq(const int* p) {
    int v;
    asm volatile("ld.acquire.gpu.b32 %0, [%1];" : "=r"(v) : "l"(p) : "memory");
    return v;
}
__device__ __forceinline__ void st_rel(int* p, int v) {
    asm volatile("st.release.gpu.b32 [%0], %1;" :: "l"(p), "r"(v) : "memory");
}
__device__ __forceinline__ void spin_ge(const int* p, int tgt) {
    while (ld_acq(p) < tgt) __nanosleep(64);
}

// ---------------------------------------------------------------------------
// Kernel 1: gi0 for layer 0 of both GRUs. grid = (T, 2 halves, 2 models).
// ---------------------------------------------------------------------------
#define GI0_SMEM ((Dn * WSTR + HB * Dn) * 4)

__global__ void __launch_bounds__(256, 1) gi0_kernel(
    const float* __restrict__ ctx,
    const float* __restrict__ encW0, const float* __restrict__ decW0,
    const float* __restrict__ encB,  const float* __restrict__ decB)
{
    extern __shared__ float sm[];
    float* W_s = sm;                 // [Dn][WSTR] transposed
    float* x_s = W_s + Dn * WSTR;    // [HB][Dn]

    const int t = blockIdx.x, half = blockIdx.y, m = blockIdx.z;
    const float* W0 = m ? decW0 : encW0;
    const float* bi = m ? decB  : encB;
    const int tid = threadIdx.x;
    const int warp = tid >> 5, lane = tid & 31;
    const int bb = warp * 8, jj = lane * 2;

    for (int idx = tid; idx < G3H * Dn; idx += 256) {
        int j = idx >> 7, k = idx & 127;
        W_s[k * WSTR + j] = W0[idx];
    }
    const int tt = m ? (t - 1) : t;
    if (m && t == 0) {
        for (int idx = tid; idx < HB * Dn; idx += 256) x_s[idx] = 0.f;
    } else {
        for (int idx = tid; idx < HB * Dn; idx += 256) {
            int b = idx >> 7, k = idx & 127;
            x_s[idx] = ctx[((size_t)(half * HB + b) * Tn + tt) * Dn + k];
        }
    }
    __syncthreads();

    u64 ar[8], az[8], an[8];
#pragma unroll
    for (int i = 0; i < 8; i++) { ar[i] = 0ull; az[i] = 0ull; an[i] = 0ull; }

    for (int k0 = 0; k0 < Dn; k0 += 4) {
        u64 wr[4], wz[4], wn[4];
#pragma unroll
        for (int kk = 0; kk < 4; kk++) {
            const float* wrow = &W_s[(k0 + kk) * WSTR];
            wr[kk] = ld2(&wrow[jj]);
            wz[kk] = ld2(&wrow[64 + jj]);
            wn[kk] = ld2(&wrow[128 + jj]);
        }
#pragma unroll
        for (int i = 0; i < 8; i++) {
            float4 xv = *(const float4*)&x_s[(bb + i) * Dn + k0];
            u64 xp[4] = {pack2(xv.x), pack2(xv.y), pack2(xv.z), pack2(xv.w)};
#pragma unroll
            for (int kk = 0; kk < 4; kk++) {
                fma2(ar[i], xp[kk], wr[kk]);
                fma2(az[i], xp[kk], wz[kk]);
                fma2(an[i], xp[kk], wn[kk]);
            }
        }
    }
    float2 br = *(const float2*)&bi[jj];
    float2 bz = *(const float2*)&bi[64 + jj];
    float2 bn = *(const float2*)&bi[128 + jj];
#pragma unroll
    for (int i = 0; i < 8; i++) {
        int bg = half * HB + bb + i;
        float* dst = &g_gi0[m][t][bg][0];
        float2 vr = unpack2(ar[i]), vz = unpack2(az[i]), vn = unpack2(an[i]);
        *(float2*)&dst[jj]       = make_float2(vr.x + br.x, vr.y + br.y);
        *(float2*)&dst[64 + jj]  = make_float2(vz.x + bz.x, vz.y + bz.y);
        *(float2*)&dst[128 + jj] = make_float2(vn.x + bn.x, vn.y + bn.y);
    }
}

// ---------------------------------------------------------------------------
// Kernel 2: persistent wavefront GRU stack (encoder then decoder).
// 512 threads; warp = (row-group, j-half); double-buffered h_s/x_s so only
// 2 barriers per step. L0 reads gi0 directly in the epilogue (no x buffer).
// ---------------------------------------------------------------------------
#define WAVE_SMEM ((2 * Hn * WSTR + 4 * HB * Hn + 4 * Hn) * 4)

__device__ __forceinline__ void stage_weights(
    float* Wih_s, float* Whh_s, float* cr_s, float* cz_s,
    float* bin_s, float* bhn_s,
    const float* __restrict__ Wih, const float* __restrict__ Whh,
    const float* __restrict__ bih, const float* __restrict__ bhh,
    int layer, bool isL0, int tid)
{
    if (!isL0) {
        const float* src = Wih + (size_t)(layer - 1) * G3H * Hn;
        for (int idx = tid; idx < G3H * Hn; idx += WTH) {
            int j = idx >> 6, k = idx & 63;
            Wih_s[k * WSTR + j] = src[idx];
        }
    }
    const float* srch = Whh + (size_t)layer * G3H * Hn;
    for (int idx = tid; idx < G3H * Hn; idx += WTH) {
        int j = idx >> 6, k = idx & 63;
        Whh_s[k * WSTR + j] = srch[idx];
    }
    if (tid < Hn) {
        int hj = tid;
        const float* bi = bih + layer * G3H;
        const float* bh = bhh + layer * G3H;
        cr_s[hj]  = (isL0 ? 0.f : bi[hj])      + bh[hj];
        cz_s[hj]  = (isL0 ? 0.f : bi[64 + hj]) + bh[64 + hj];
        bin_s[hj] = (isL0 ? 0.f : bi[128 + hj]);
        bhn_s[hj] = bh[128 + hj];
    }
}

__global__ void __launch_bounds__(WTH, 1) gru_wave(
    const float* __restrict__ encWih, const float* __restrict__ encWhh,
    const float* __restrict__ encBih, const float* __restrict__ encBhh,
    const float* __restrict__ decWih, const float* __restrict__ decWhh,
    const float* __restrict__ decBih, const float* __restrict__ decBhh)
{
    extern __shared__ float sm[];
    float* Wih_s = sm;                        // [64][WSTR]
    float* Whh_s = Wih_s + Hn * WSTR;         // [64][WSTR]
    float* h_buf = Whh_s + Hn * WSTR;         // [2][HB*Hn]
    float* x_buf = h_buf + 2 * HB * Hn;       // [2][HB*Hn] (layers>0)
    float* cr_s  = x_buf + 2 * HB * Hn;
    float* cz_s  = cr_s + Hn;
    float* bin_s = cz_s + Hn;
    float* bhn_s = bin_s + Hn;

    const int tid   = threadIdx.x;
    const int cta   = blockIdx.x;
    const int layer = cta >> 1;
    const int half  = cta & 1;
    const bool isL0 = (layer == 0);
    const int warp = tid >> 5, lane = tid & 31;
    const int rg = warp >> 1;
    const int jh = warp & 1;
    const int bb = rg * 8 + (lane >> 4) * 4;
    const int jj = jh * 32 + (lane & 15) * 2;

    int base = ld_acq(&g_prog[cta]);

    for (int i = tid; i < 2 * HB * Hn; i += WTH) h_buf[i] = 0.f;  // h0 = 0
    stage_weights(Wih_s, Whh_s, cr_s, cz_s, bin_s, bhn_s,
                  encWih, encWhh, encBih, encBhh, layer, isL0, tid);
    // prologue: stage x(0) for layers > 0
    if (!isL0) {
        spin_ge(&g_prog[cta - 2], base + 1);
        const float4* src = (const float4*)&g_xbuf[layer - 1][half][0][0][0];
        float4* dst = (float4*)x_buf;
        for (int i = tid; i < HB * Hn / 4; i += WTH) dst[i] = __ldcg(&src[i]);
    }
    __syncthreads();

    for (int t = 0; t < 2 * Tn; ++t) {
        if (t == Tn) {   // encoder -> decoder: swap weights, keep h (= h_n)
            stage_weights(Wih_s, Whh_s, cr_s, cz_s, bin_s, bhn_s,
                          decWih, decWhh, decBih, decBhh, layer, isL0, tid);
            __syncthreads();
        }
        const float* hc = h_buf + (t & 1) * HB * Hn;        // read buffer
        float* hnx      = h_buf + ((t + 1) & 1) * HB * Hn;  // write buffer
        const float* xc = x_buf + (t & 1) * HB * Hn;

        // ---- GEMMs (packed f32x2) ----
        u64 ar[4], az[4], an[4], ahn[4];
#pragma unroll
        for (int i = 0; i < 4; i++) {
            ar[i] = 0ull; az[i] = 0ull; an[i] = 0ull; ahn[i] = 0ull;
        }

        if (!isL0) {
            for (int k0 = 0; k0 < Hn; k0 += 4) {
                u64 wr[4], wz[4], wn[4], ur[4], uz[4], un[4];
#pragma unroll
                for (int kk = 0; kk < 4; kk++) {
                    const float* a = &Wih_s[(k0 + kk) * WSTR];
                    const float* b = &Whh_s[(k0 + kk) * WSTR];
                    wr[kk] = ld2(&a[jj]);
                    wz[kk] = ld2(&a[64 + jj]);
                    wn[kk] = ld2(&a[128 + jj]);
                    ur[kk] = ld2(&b[jj]);
                    uz[kk] = ld2(&b[64 + jj]);
                    un[kk] = ld2(&b[128 + jj]);
                }
#pragma unroll
                for (int i = 0; i < 4; i++) {
                    float4 xv = *(const float4*)&xc[(bb + i) * Hn + k0];
                    float4 hv = *(const float4*)&hc[(bb + i) * Hn + k0];
                    float xk[4] = {xv.x, xv.y, xv.z, xv.w};
                    float hk[4] = {hv.x, hv.y, hv.z, hv.w};
#pragma unroll
                    for (int kk = 0; kk < 4; kk++) {
                        u64 xp = pack2(xk[kk]);
                        u64 hp = pack2(hk[kk]);
                        fma2(ar[i], xp, wr[kk]);
                        fma2(ar[i], hp, ur[kk]);
                        fma2(az[i], xp, wz[kk]);
                        fma2(az[i], hp, uz[kk]);
                        fma2(an[i], xp, wn[kk]);
                        fma2(ahn[i], hp, un[kk]);
                    }
                }
            }
        } else {
            for (int k0 = 0; k0 < Hn; k0 += 4) {
                u64 ur[4], uz[4], un[4];
#pragma unroll
                for (int kk = 0; kk < 4; kk++) {
                    const float* b = &Whh_s[(k0 + kk) * WSTR];
                    ur[kk] = ld2(&b[jj]);
                    uz[kk] = ld2(&b[64 + jj]);
                    un[kk] = ld2(&b[128 + jj]);
                }
#pragma unroll
                for (int i = 0; i < 4; i++) {
                    float4 hv = *(const float4*)&hc[(bb + i) * Hn + k0];
                    float hk[4] = {hv.x, hv.y, hv.z, hv.w};
#pragma unroll
                    for (int kk = 0; kk < 4; kk++) {
                        u64 hp = pack2(hk[kk]);
                        fma2(ar[i], hp, ur[kk]);
                        fma2(az[i], hp, uz[kk]);
                        fma2(ahn[i], hp, un[kk]);
                    }
                }
            }
        }

        // ---- epilogue (no barrier needed: writes go to hnx buffer) ----
        const bool wring = (layer < Ln - 1);
        const bool wtop  = (layer == Ln - 1) && (t >= Tn);
        float* rdst = &g_xbuf[layer][half][t & (RINGN - 1)][0][0];
        float* tdst = wtop ? &g_dectop[t - Tn][half * HB][0] : rdst;
        float2 crv = *(const float2*)&cr_s[jj];
        float2 czv = *(const float2*)&cz_s[jj];
        float2 biv = *(const float2*)&bin_s[jj];
        float2 bhv = *(const float2*)&bhn_s[jj];

        // L0: prefetch gi0 gate slices straight from global (L2-resident)
        float2 gx[4][3];
        if (isL0) {
            int m  = (t < Tn) ? 0 : 1;
            int tt = (t < Tn) ? t : t - Tn;
#pragma unroll
            for (int i = 0; i < 4; i++) {
                const float* gp = &g_gi0[m][tt][half * HB + bb + i][0];
                gx[i][0] = *(const float2*)&gp[jj];
                gx[i][1] = *(const float2*)&gp[64 + jj];
                gx[i][2] = *(const float2*)&gp[128 + jj];
            }
        }

        // backpressure: slot (t & 3) may be overwritten once downstream
        // has consumed step t - RINGN
        if (wring && t >= RINGN)
            spin_ge(&g_prog[cta + 2], base + t - RINGN + 1);

#pragma unroll
        for (int i = 0; i < 4; i++) {
            int b = bb + i;
            float2 vr = unpack2(ar[i]);
            float2 vz = unpack2(az[i]);
            float2 vn = unpack2(an[i]);
            float2 vh = unpack2(ahn[i]);
            float arr[2] = {vr.x, vr.y}, azz[2] = {vz.x, vz.y};
            float ann[2] = {vn.x, vn.y}, ahh[2] = {vh.x, vh.y};
            float crr[2] = {crv.x, crv.y}, czz[2] = {czv.x, czv.y};
            float bii[2] = {biv.x, biv.y}, bhh2[2] = {bhv.x, bhv.y};
            float gxr[2] = {gx[i][0].x, gx[i][0].y};
            float gxz[2] = {gx[i][1].x, gx[i][1].y};
            float gxn[2] = {gx[i][2].x, gx[i][2].y};
            float hnew2[2];
#pragma unroll
            for (int p = 0; p < 2; p++) {
                int hj = jj + p;
                float xr, xz, xn;
                if (isL0) { xr = gxr[p]; xz = gxz[p]; xn = gxn[p]; }
                else      { xr = 0.f; xz = 0.f; xn = ann[p]; }
                float r = sigf(arr[p] + xr + crr[p]);
                float z = sigf(azz[p] + xz + czz[p]);
                float n = tanhf_fast(xn + bii[p] + r * (ahh[p] + bhh2[p]));
                float hold = hc[b * Hn + hj];
                hnew2[p] = (1.0f - z) * n + z * hold;
            }
            float2 hw = make_float2(hnew2[0], hnew2[1]);
            *(float2*)&hnx[b * Hn + jj] = hw;
            if (wring) *(float2*)&rdst[b * Hn + jj] = hw;
            if (wtop)  *(float2*)&tdst[b * Hn + jj] = hw;
        }
        __syncthreads();   // BAR_e: ring/hnx writes complete
        if (tid == 0) st_rel(&g_prog[cta], base + t + 1);   // early release

        // ---- stage x(t+1) into the idle buffer (layers > 0) ----
        if (!isL0 && t + 1 < 2 * Tn) {
            spin_ge(&g_prog[cta - 2], base + t + 2);
            const float4* src = (const float4*)
                &g_xbuf[layer - 1][half][(t + 1) & (RINGN - 1)][0][0];
            float4* dst = (float4*)(x_buf + ((t + 1) & 1) * HB * Hn);
            for (int i = tid; i < HB * Hn / 4; i += WTH)
                dst[i] = __ldcg(&src[i]);
        }
        __syncthreads();   // BAR_d: staged x + hnx visible for next GEMM
    }
}

// ---------------------------------------------------------------------------
// Kernel 3: output projection  out = dec_top @ Wo^T + bo. grid = (T, 2).
// ---------------------------------------------------------------------------
#define PSTR 130
#define PROJ_SMEM ((Hn * PSTR + HB * Hn) * 4)

__global__ void __launch_bounds__(256, 1) proj_kernel(
    const float* __restrict__ Wo, const float* __restrict__ bo,
    float* __restrict__ out)
{
    extern __shared__ float sm[];
    float* W_s = sm;                 // [64][PSTR] transposed
    float* x_s = W_s + Hn * PSTR;    // [HB][Hn]

    const int t = blockIdx.x, half = blockIdx.y;
    const int tid = threadIdx.x;
    const int warp = tid >> 5, lane = tid & 31;
    const int bb = warp * 8, jj = lane * 2;

    for (int idx = tid; idx < Dn * Hn; idx += 256) {
        int d = idx >> 6, k = idx & 63;
        W_s[k * PSTR + d] = Wo[idx];
    }
    for (int idx = tid; idx < HB * Hn; idx += 256) {
        x_s[idx] = g_dectop[t][half * HB + (idx >> 6)][idx & 63];
    }
    __syncthreads();

    u64 a0[8], a1[8];
#pragma unroll
    for (int i = 0; i < 8; i++) { a0[i] = 0ull; a1[i] = 0ull; }

    for (int k0 = 0; k0 < Hn; k0 += 4) {
        u64 w0[4], w1[4];
#pragma unroll
        for (int kk = 0; kk < 4; kk++) {
            const float* wrow = &W_s[(k0 + kk) * PSTR];
            w0[kk] = ld2(&wrow[jj]);
            w1[kk] = ld2(&wrow[64 + jj]);
        }
#pragma unroll
        for (int i = 0; i < 8; i++) {
            float4 xv = *(const float4*)&x_s[(bb + i) * Hn + k0];
            u64 xp[4] = {pack2(xv.x), pack2(xv.y), pack2(xv.z), pack2(xv.w)};
#pragma unroll
            for (int kk = 0; kk < 4; kk++) {
                fma2(a0[i], xp[kk], w0[kk]);
                fma2(a1[i], xp[kk], w1[kk]);
            }
        }
    }
    float2 b0 = *(const float2*)&bo[jj];
    float2 b1 = *(const float2*)&bo[64 + jj];
#pragma unroll
    for (int i = 0; i < 8; i++) {
        int bg = half * HB + bb + i;
        float* o = &out[((size_t)bg * Tn + t) * Dn];
        float2 v0 = unpack2(a0[i]), v1 = unpack2(a1[i]);
        *(float2*)&o[jj]      = make_float2(v0.x + b0.x, v0.y + b0.y);
        *(float2*)&o[64 + jj] = make_float2(v1.x + b1.x, v1.y + b1.y);
    }
}

// ---------------------------------------------------------------------------
extern "C" void kernel_launch(void* const* d_in, const int* in_sizes, int n_in,
                              void* d_out, int out_size) {
    const float* ctx     = (const float*)d_in[0];
    const float* encW0   = (const float*)d_in[1];
    const float* encWih  = (const float*)d_in[2];
    const float* encWhh  = (const float*)d_in[3];
    const float* encBih  = (const float*)d_in[4];
    const float* encBhh  = (const float*)d_in[5];
    const float* decW0   = (const float*)d_in[6];
    const float* decWih  = (const float*)d_in[7];
    const float* decWhh  = (const float*)d_in[8];
    const float* decBih  = (const float*)d_in[9];
    const float* decBhh  = (const float*)d_in[10];
    const float* Wo      = (const float*)d_in[11];
    const float* bo      = (const float*)d_in[12];
    float* out = (float*)d_out;

    cudaFuncSetAttribute(gi0_kernel,
        cudaFuncAttributeMaxDynamicSharedMemorySize, GI0_SMEM);
    cudaFuncSetAttribute(gru_wave,
        cudaFuncAttributeMaxDynamicSharedMemorySize, WAVE_SMEM);
    cudaFuncSetAttribute(proj_kernel,
        cudaFuncAttributeMaxDynamicSharedMemorySize, PROJ_SMEM);

    gi0_kernel<<<dim3(Tn, 2, 2), 256, GI0_SMEM>>>(ctx, encW0, decW0,
                                                  encBih, decBih);
    gru_wave<<<Ln * 2, WTH, WAVE_SMEM>>>(encWih, encWhh, encBih, encBhh,
                                         decWih, decWhh, decBih, decBhh);
    proj_kernel<<<dim3(Tn, 2), 256, PROJ_SMEM>>>(Wo, bo, out);
}